// round 15
// baseline (speedup 1.0000x reference)
#include <cuda_runtime.h>

#define Hh 64
#define FF 36
#define Ww 8
#define Ss 200
#define OPAD 40            // o padded to 40 (rows 36..39 zero)
#define MSTR 36            // M row stride (words): B-LDS bank 4g+t2 -> conflict-free
#define KSTR 68            // K row stride (floats): A-LDS.64 bank 4g+2t2 -> 2-phase min
#define NT 416             // 13 warps = 13 m-tiles

// smem offsets (floats)
#define OFF_K    0                    // 200*68 = 13600
#define OFF_MHI  13600                // 40*36  = 1440 (unsigned)
#define OFF_MLO  15040                // 1440
#define OFF_E    16480                // 200
#define OFF_RED  16680                // 384
#define OFF_D    17064                // 40
#define OFF_W2   17104                // 40
#define OFF_Q    17144                // 64
#define OFF_MISC 17208                // 4: smax, ssum, prelu_a, b2
#define OFF_MK   17212                // 200 mask flags
#define OFF_FLAG 17412                // 1 (int: mask-is-bytes)
#define SMEM_FLOATS 17413             // 69.7 KB -> 2 CTAs/SM

__device__ __forceinline__ unsigned cvt_bf16x2(float f1, float f0) {
    unsigned r;
    asm("cvt.rn.bf16x2.f32 %0, %1, %2;" : "=r"(r) : "f"(f1), "f"(f0));
    return r;
}
__device__ __forceinline__ float bf16lo_f32(unsigned v) {
    return __uint_as_float(v << 16);
}
__device__ __forceinline__ float bf16hi_f32(unsigned v) {
    return __uint_as_float(v & 0xFFFF0000u);
}
__device__ __forceinline__ void mma_bf16(float* c, const unsigned* a,
                                         unsigned b0, unsigned b1) {
    asm volatile(
        "mma.sync.aligned.m16n8k16.row.col.f32.bf16.bf16.f32 "
        "{%0,%1,%2,%3}, {%4,%5,%6,%7}, {%8,%9}, {%0,%1,%2,%3};"
        : "+f"(c[0]), "+f"(c[1]), "+f"(c[2]), "+f"(c[3])
        : "r"(a[0]), "r"(a[1]), "r"(a[2]), "r"(a[3]), "r"(b0), "r"(b1));
}

extern "C" __global__ void __launch_bounds__(NT, 2)
twb_all(const float* __restrict__ query,
        const float* __restrict__ key,
        const float* __restrict__ W1,
        const float* __restrict__ b1,
        const float* __restrict__ prelu_a,
        const float* __restrict__ W2,
        const float* __restrict__ b2,
        const void* __restrict__ mask,
        float* __restrict__ out)
{
    extern __shared__ float sm[];
    unsigned* Mhi = (unsigned*)&sm[OFF_MHI];
    unsigned* Mlo = (unsigned*)&sm[OFF_MLO];
    int* flag = (int*)&sm[OFF_FLAG];

    const int b   = blockIdx.x;
    const int tid = threadIdx.x;
    const int lane = tid & 31;
    const int g    = lane >> 2;
    const int t2   = lane & 3;
    const int mt   = tid >> 5;          // warp = m-tile, 0..12
    const int mb   = mt * 16;

    // ===== phase 0 (once per b): q, W2, scalars, mask-layout, M, d =====
    if (tid < Hh) sm[OFF_Q + tid]  = query[b * Hh + tid];
    if (tid < OPAD) sm[OFF_W2 + tid] = (tid < FF) ? W2[tid] : 0.f;
    if (tid == 0) {
        sm[OFF_MISC + 2] = *prelu_a;
        sm[OFF_MISC + 3] = *b2;
        *flag = 0;
    }
    __syncthreads();

    // mask-layout scan: first 1024 words (safe under both layouts)
    {
        int f = 0;
        const unsigned* mw = (const unsigned*)mask;
        for (int i = tid; i < 1024; i += NT) f |= (mw[i] > 1u);
        if (f) atomicOr(flag, 1);
    }

    // build M (bf16 hi/lo, stride 36) and d from W1, q
    {
        const float* q = &sm[OFF_Q];
        for (int idx = tid; idx < OPAD * 32; idx += NT) {
            int o = idx >> 5, p = idx & 31;
            float m0 = 0.f, m1 = 0.f;
            if (o < FF) {
                const float* w = W1 + o * 4 * Hh;
                int h0 = 2 * p, h1 = 2 * p + 1;
                m0 = w[Hh + h0] - w[2 * Hh + h0] + w[3 * Hh + h0] * q[h0];
                m1 = w[Hh + h1] - w[2 * Hh + h1] + w[3 * Hh + h1] * q[h1];
            }
            unsigned hi2 = cvt_bf16x2(m1, m0);
            unsigned lo2 = cvt_bf16x2(m1 - bf16hi_f32(hi2), m0 - bf16lo_f32(hi2));
            Mhi[o * MSTR + p] = hi2;
            Mlo[o * MSTR + p] = lo2;
        }
        if (tid < OPAD) {
            float acc = 0.f;
            if (tid < FF) {
                const float* w = W1 + tid * 4 * Hh;
                acc = b1[tid];
                #pragma unroll 8
                for (int h = 0; h < Hh; h++)
                    acc += (w[h] + w[2 * Hh + h]) * q[h];
            }
            sm[OFF_D + tid] = acc;
        }
    }
    __syncthreads();
    const int mask_bytes = *flag;
    const float ap  = sm[OFF_MISC + 2];
    const float bb2 = sm[OFF_MISC + 3];

    // ===== loop over 8 windows (same b -> M reused) =====
    for (int w = 0; w < Ww; w++) {
        const int bw = b * Ww + w;
        const float* kb = key + (size_t)bw * Ss * Hh;

        // mask flags for this bw
        if (tid < Ss) {
            int mk = mask_bytes
                   ? ((const unsigned char*)mask)[(size_t)bw * Ss + tid]
                   : ((const int*)mask)[(size_t)bw * Ss + tid];
            sm[OFF_MK + tid] = mk ? 1.f : 0.f;
        }

        // K tile: 16 LDG.64/thread -> STS (kp transient)
        {
            float2 kp[4][4];
            #pragma unroll
            for (int kt = 0; kt < 4; kt++)
                #pragma unroll
                for (int j = 0; j < 4; j++) {
                    int row = mb + g + (j & 1) * 8;
                    int col = kt * 16 + 2 * t2 + (j >> 1) * 8;
                    kp[kt][j] = (row < Ss)
                        ? *(const float2*)(kb + row * Hh + col)
                        : make_float2(0.f, 0.f);
                }
            #pragma unroll
            for (int kt = 0; kt < 4; kt++)
                #pragma unroll
                for (int j = 0; j < 4; j++) {
                    int row = mb + g + (j & 1) * 8;
                    int col = kt * 16 + 2 * t2 + (j >> 1) * 8;
                    if (row < Ss)
                        *(float2*)&sm[OFF_K + row * KSTR + col] = kp[kt][j];
                }
        }
        __syncthreads();

        // bf16x3 mma: A fragments re-read from smem K (kt-transient regs)
        float acc[5][4];
        #pragma unroll
        for (int nt = 0; nt < 5; nt++)
            #pragma unroll
            for (int j = 0; j < 4; j++) acc[nt][j] = 0.f;

        #pragma unroll
        for (int kt = 0; kt < 4; kt++) {
            unsigned ahi[4], alo[4];
            #pragma unroll
            for (int j = 0; j < 4; j++) {
                int row = mb + g + (j & 1) * 8;
                int col = kt * 16 + 2 * t2 + (j >> 1) * 8;
                float2 kv = (row < Ss)
                    ? *(const float2*)&sm[OFF_K + row * KSTR + col]
                    : make_float2(0.f, 0.f);
                unsigned hi2 = cvt_bf16x2(kv.y, kv.x);
                ahi[j] = hi2;
                alo[j] = cvt_bf16x2(kv.y - bf16hi_f32(hi2),
                                    kv.x - bf16lo_f32(hi2));
            }
            #pragma unroll
            for (int nt = 0; nt < 5; nt++) {
                int o = nt * 8 + g;
                int p = kt * 8 + t2;
                unsigned bh0 = Mhi[o * MSTR + p];
                unsigned bh1 = Mhi[o * MSTR + p + 4];
                unsigned bl0 = Mlo[o * MSTR + p];
                unsigned bl1 = Mlo[o * MSTR + p + 4];
                mma_bf16(acc[nt], ahi, bh0, bh1);   // khi*mhi
                mma_bf16(acc[nt], alo, bh0, bh1);   // klo*mhi
                mma_bf16(acc[nt], ahi, bl0, bl1);   // khi*mlo
            }
        }

        // score epilogue: PReLU + W2 dot, 4-lane reduce, mask, e[]
        {
            float p0 = 0.f, p1 = 0.f;
            #pragma unroll
            for (int nt = 0; nt < 5; nt++) {
                #pragma unroll
                for (int j = 0; j < 2; j++) {
                    int o = nt * 8 + 2 * t2 + j;
                    float dv = sm[OFF_D + o], wv = sm[OFF_W2 + o];
                    float h0 = acc[nt][j] + dv;
                    h0 = h0 >= 0.f ? h0 : ap * h0;
                    p0 += wv * h0;
                    float h1 = acc[nt][2 + j] + dv;
                    h1 = h1 >= 0.f ? h1 : ap * h1;
                    p1 += wv * h1;
                }
            }
            p0 += __shfl_xor_sync(0xffffffffu, p0, 1);
            p0 += __shfl_xor_sync(0xffffffffu, p0, 2);
            p1 += __shfl_xor_sync(0xffffffffu, p1, 1);
            p1 += __shfl_xor_sync(0xffffffffu, p1, 2);
            if (t2 == 0) {
                int s0 = mb + g, s1 = mb + g + 8;
                if (s0 < Ss)
                    sm[OFF_E + s0] = (sm[OFF_MK + s0] != 0.f) ? -10000.0f
                                                              : (p0 + bb2);
                if (s1 < Ss)
                    sm[OFF_E + s1] = (sm[OFF_MK + s1] != 0.f) ? -10000.0f
                                                              : (p1 + bb2);
            }
        }
        __syncthreads();

        // softmax over S
        if (tid < 32) {
            float m = -3.4e38f;
            for (int i = tid; i < Ss; i += 32) m = fmaxf(m, sm[OFF_E + i]);
            #pragma unroll
            for (int off = 16; off; off >>= 1)
                m = fmaxf(m, __shfl_xor_sync(0xffffffffu, m, off));
            if (tid == 0) sm[OFF_MISC + 0] = m;
        }
        __syncthreads();
        const float smax = sm[OFF_MISC + 0];
        if (tid < Ss) sm[OFF_E + tid] = __expf(sm[OFF_E + tid] - smax);
        __syncthreads();
        if (tid < 32) {
            float s = 0.f;
            for (int i = tid; i < Ss; i += 32) s += sm[OFF_E + i];
            #pragma unroll
            for (int off = 16; off; off >>= 1)
                s += __shfl_xor_sync(0xffffffffu, s, off);
            if (tid == 0) sm[OFF_MISC + 1] = s;
        }
        __syncthreads();
        const float inv = 1.0f / sm[OFF_MISC + 1];

        // weighted sum from smem K: 6 s-groups x 64 h (384 threads)
        if (tid < 384) {
            int h = tid & 63, sg = tid >> 6;
            float a2 = 0.f;
            for (int s = sg; s < Ss; s += 6)
                a2 += sm[OFF_E + s] * sm[OFF_K + s * KSTR + h];
            sm[OFF_RED + sg * 64 + h] = a2;
        }
        __syncthreads();
        if (tid < Hh) {
            float v = 0.f;
            #pragma unroll
            for (int sg = 0; sg < 6; sg++) v += sm[OFF_RED + sg * 64 + tid];
            out[(size_t)bw * Hh + tid] = v * inv;
        }
        __syncthreads();   // protect Ksm/e/mkf before next w overwrites
    }
}

extern "C" void kernel_launch(void* const* d_in, const int* in_sizes, int n_in,
                              void* d_out, int out_size) {
    const float* query          = (const float*)d_in[0];
    const float* key            = (const float*)d_in[1];
    const float* W1             = (const float*)d_in[2];
    const float* b1             = (const float*)d_in[3];
    const float* prelu_a        = (const float*)d_in[4];
    const float* W2             = (const float*)d_in[5];
    const float* b2             = (const float*)d_in[6];
    const void*  mask           = (const void*)d_in[7];
    float* out = (float*)d_out;

    const int smem_bytes = SMEM_FLOATS * sizeof(float);   // ~69.7 KB
    cudaFuncSetAttribute(twb_all,
                         cudaFuncAttributeMaxDynamicSharedMemorySize, smem_bytes);
    twb_all<<<512, NT, smem_bytes>>>(query, key, W1, b1, prelu_a, W2, b2,
                                     mask, out);
}

// round 16
// speedup vs baseline: 1.0953x; 1.0953x over previous
#include <cuda_runtime.h>

#define Hh 64
#define FF 36
#define Ww 8
#define Ss 200
#define OPAD 40            // o padded to 40 (rows 36..39 zero)
#define MSTR 36            // M row stride (words): B-LDS bank 4g+t2 -> conflict-free
#define KSTR 68            // K row stride (floats)
#define NT 416             // 13 warps = 13 m-tiles

// smem offsets (floats)
#define OFF_K    0                    // 200*68 = 13600
#define OFF_MHI  13600                // 40*36  = 1440 (unsigned)
#define OFF_MLO  15040                // 1440
#define OFF_E    16480                // 200
#define OFF_RED  16680                // 384
#define OFF_D    17064                // 40
#define OFF_W2   17104                // 40
#define OFF_Q    17144                // 64
#define OFF_WMAX 17208                // 16 (13 used)
#define OFF_WSUM 17224                // 16
#define OFF_MISC 17240                // 2: prelu_a, b2
#define OFF_FLAG 17242                // 1 (int)
#define SMEM_FLOATS 17243             // 69.0 KB -> 2 CTAs/SM

__device__ __forceinline__ unsigned cvt_bf16x2(float f1, float f0) {
    unsigned r;
    asm("cvt.rn.bf16x2.f32 %0, %1, %2;" : "=r"(r) : "f"(f1), "f"(f0));
    return r;
}
__device__ __forceinline__ float bf16lo_f32(unsigned v) {
    return __uint_as_float(v << 16);
}
__device__ __forceinline__ float bf16hi_f32(unsigned v) {
    return __uint_as_float(v & 0xFFFF0000u);
}
__device__ __forceinline__ void mma_bf16(float* c, const unsigned* a,
                                         unsigned b0, unsigned b1) {
    asm volatile(
        "mma.sync.aligned.m16n8k16.row.col.f32.bf16.bf16.f32 "
        "{%0,%1,%2,%3}, {%4,%5,%6,%7}, {%8,%9}, {%0,%1,%2,%3};"
        : "+f"(c[0]), "+f"(c[1]), "+f"(c[2]), "+f"(c[3])
        : "r"(a[0]), "r"(a[1]), "r"(a[2]), "r"(a[3]), "r"(b0), "r"(b1));
}

// 16 independent LDG.64 of this warp's m-tile rows (rows >= 200 zeroed)
__device__ __forceinline__ void load_kp(float2 kp[4][4], const float* kb,
                                        int mb, int g, int t2) {
    #pragma unroll
    for (int kt = 0; kt < 4; kt++)
        #pragma unroll
        for (int j = 0; j < 4; j++) {
            int row = mb + g + (j & 1) * 8;
            int col = kt * 16 + 2 * t2 + (j >> 1) * 8;
            kp[kt][j] = (row < Ss)
                ? *(const float2*)(kb + row * Hh + col)
                : make_float2(0.f, 0.f);
        }
}

extern "C" __global__ void __launch_bounds__(NT, 2)
twb_all(const float* __restrict__ query,
        const float* __restrict__ key,
        const float* __restrict__ W1,
        const float* __restrict__ b1,
        const float* __restrict__ prelu_a,
        const float* __restrict__ W2,
        const float* __restrict__ b2,
        const void* __restrict__ mask,
        float* __restrict__ out)
{
    extern __shared__ float sm[];
    unsigned* Mhi = (unsigned*)&sm[OFF_MHI];
    unsigned* Mlo = (unsigned*)&sm[OFF_MLO];
    int* flag = (int*)&sm[OFF_FLAG];

    const int b    = blockIdx.x;
    const int tid  = threadIdx.x;
    const int lane = tid & 31;
    const int g    = lane >> 2;
    const int t2   = lane & 3;
    const int mt   = tid >> 5;          // warp = m-tile, 0..12
    const int mb   = mt * 16;
    const int s0   = mb + g;            // always < 200
    const int s1   = mb + g + 8;        // may be >= 200 (mt==12)

    // ===== phase 0 (once per b) =====
    if (tid < Hh) sm[OFF_Q + tid]  = query[b * Hh + tid];
    if (tid < OPAD) sm[OFF_W2 + tid] = (tid < FF) ? W2[tid] : 0.f;
    if (tid == 0) {
        sm[OFF_MISC + 0] = *prelu_a;
        sm[OFF_MISC + 1] = *b2;
        *flag = 0;
    }

    // prefetch w=0 K tile into registers (overlaps M build)
    float2 kp[4][4];
    load_kp(kp, key + (size_t)(b * Ww) * Ss * Hh, mb, g, t2);

    __syncthreads();

    // mask-layout scan: first 1024 words (safe under both layouts)
    {
        int f = 0;
        const unsigned* mw = (const unsigned*)mask;
        for (int i = tid; i < 1024; i += NT) f |= (mw[i] > 1u);
        if (f) atomicOr(flag, 1);
    }

    // build M (bf16 hi/lo, stride 36) and d from W1, q
    {
        const float* q = &sm[OFF_Q];
        for (int idx = tid; idx < OPAD * 32; idx += NT) {
            int o = idx >> 5, p = idx & 31;
            float m0 = 0.f, m1 = 0.f;
            if (o < FF) {
                const float* w = W1 + o * 4 * Hh;
                int h0 = 2 * p, h1 = 2 * p + 1;
                m0 = w[Hh + h0] - w[2 * Hh + h0] + w[3 * Hh + h0] * q[h0];
                m1 = w[Hh + h1] - w[2 * Hh + h1] + w[3 * Hh + h1] * q[h1];
            }
            unsigned hi2 = cvt_bf16x2(m1, m0);
            unsigned lo2 = cvt_bf16x2(m1 - bf16hi_f32(hi2), m0 - bf16lo_f32(hi2));
            Mhi[o * MSTR + p] = hi2;
            Mlo[o * MSTR + p] = lo2;
        }
        if (tid < OPAD) {
            float acc = 0.f;
            if (tid < FF) {
                const float* w = W1 + tid * 4 * Hh;
                acc = b1[tid];
                #pragma unroll 8
                for (int h = 0; h < Hh; h++)
                    acc += (w[h] + w[2 * Hh + h]) * q[h];
            }
            sm[OFF_D + tid] = acc;
        }
    }
    __syncthreads();
    const int mask_bytes = *flag;
    const float ap  = sm[OFF_MISC + 0];
    const float bb2 = sm[OFF_MISC + 1];

    // ===== loop over 8 windows; M static, K prefetched, 3 barriers/w =====
    for (int w = 0; w < Ww; w++) {
        const int bw = b * Ww + w;

        // per-lane mask loads (issued early; consumed at epilogue)
        int mk0, mk1;
        if (mask_bytes) {
            const unsigned char* mp = (const unsigned char*)mask + (size_t)bw * Ss;
            mk0 = mp[s0];
            mk1 = (s1 < Ss) ? mp[s1] : 1;
        } else {
            const int* mp = (const int*)mask + (size_t)bw * Ss;
            mk0 = mp[s0];
            mk1 = (s1 < Ss) ? mp[s1] : 1;
        }

        // STS current K tile for the weighted-sum epilogue
        #pragma unroll
        for (int kt = 0; kt < 4; kt++)
            #pragma unroll
            for (int j = 0; j < 4; j++) {
                int row = mb + g + (j & 1) * 8;
                int col = kt * 16 + 2 * t2 + (j >> 1) * 8;
                if (row < Ss)
                    *(float2*)&sm[OFF_K + row * KSTR + col] = kp[kt][j];
            }

        // mma (no barrier needed: A from regs, M static)
        float acc[5][4];
        #pragma unroll
        for (int nt = 0; nt < 5; nt++)
            #pragma unroll
            for (int j = 0; j < 4; j++) acc[nt][j] = 0.f;

        #pragma unroll
        for (int kt = 0; kt < 4; kt++) {
            unsigned ahi[4], alo[4];
            #pragma unroll
            for (int j = 0; j < 4; j++) {
                unsigned hi2 = cvt_bf16x2(kp[kt][j].y, kp[kt][j].x);
                ahi[j] = hi2;
                alo[j] = cvt_bf16x2(kp[kt][j].y - bf16hi_f32(hi2),
                                    kp[kt][j].x - bf16lo_f32(hi2));
            }
            #pragma unroll
            for (int nt = 0; nt < 5; nt++) {
                int o = nt * 8 + g;
                int p = kt * 8 + t2;
                unsigned bh0 = Mhi[o * MSTR + p];
                unsigned bh1 = Mhi[o * MSTR + p + 4];
                unsigned bl0 = Mlo[o * MSTR + p];
                unsigned bl1 = Mlo[o * MSTR + p + 4];
                mma_bf16(acc[nt], ahi, bh0, bh1);   // khi*mhi
                mma_bf16(acc[nt], alo, bh0, bh1);   // klo*mhi
                mma_bf16(acc[nt], ahi, bl0, bl1);   // khi*mlo
            }
        }

        // prefetch next w's K tile (hidden behind epilogue+softmax+WS)
        if (w + 1 < Ww)
            load_kp(kp, key + (size_t)(bw + 1) * Ss * Hh, mb, g, t2);

        // score epilogue: PReLU + W2 dot, 4-lane reduce (replicated in group)
        float p0 = 0.f, p1 = 0.f;
        #pragma unroll
        for (int nt = 0; nt < 5; nt++) {
            #pragma unroll
            for (int j = 0; j < 2; j++) {
                int o = nt * 8 + 2 * t2 + j;
                float dv = sm[OFF_D + o], wv = sm[OFF_W2 + o];
                float h0 = acc[nt][j] + dv;
                h0 = h0 >= 0.f ? h0 : ap * h0;
                p0 += wv * h0;
                float h1 = acc[nt][2 + j] + dv;
                h1 = h1 >= 0.f ? h1 : ap * h1;
                p1 += wv * h1;
            }
        }
        p0 += __shfl_xor_sync(0xffffffffu, p0, 1);
        p0 += __shfl_xor_sync(0xffffffffu, p0, 2);
        p1 += __shfl_xor_sync(0xffffffffu, p1, 1);
        p1 += __shfl_xor_sync(0xffffffffu, p1, 2);

        // masked scores (replicated within 4-lane group)
        float q0 = mk0 ? -10000.0f : (p0 + bb2);
        float q1 = (s1 < Ss) ? (mk1 ? -10000.0f : (p1 + bb2)) : -3.0e38f;

        // warp max -> smem
        float wm = fmaxf(q0, q1);
        wm = fmaxf(wm, __shfl_xor_sync(0xffffffffu, wm, 4));
        wm = fmaxf(wm, __shfl_xor_sync(0xffffffffu, wm, 8));
        wm = fmaxf(wm, __shfl_xor_sync(0xffffffffu, wm, 16));
        if (lane == 0) sm[OFF_WMAX + mt] = wm;
        __syncthreads();                               // B1

        float bmax = -3.4e38f;
        #pragma unroll
        for (int i = 0; i < 13; i++) bmax = fmaxf(bmax, sm[OFF_WMAX + i]);

        float e0 = __expf(q0 - bmax);
        float e1 = (s1 < Ss) ? __expf(q1 - bmax) : 0.f;
        if (t2 == 0) {
            sm[OFF_E + s0] = e0;
            if (s1 < Ss) sm[OFF_E + s1] = e1;
        }
        float cs = (t2 == 0) ? (e0 + e1) : 0.f;
        #pragma unroll
        for (int off = 16; off; off >>= 1)
            cs += __shfl_xor_sync(0xffffffffu, cs, off);
        if (lane == 0) sm[OFF_WSUM + mt] = cs;
        __syncthreads();                               // B2

        float ssum = 0.f;
        #pragma unroll
        for (int i = 0; i < 13; i++) ssum += sm[OFF_WSUM + i];
        const float inv = 1.0f / ssum;

        // weighted sum from smem K: 6 s-groups x 64 h (384 threads)
        if (tid < 384) {
            int h = tid & 63, sg = tid >> 6;
            float a2 = 0.f;
            for (int s = sg; s < Ss; s += 6)
                a2 += sm[OFF_E + s] * sm[OFF_K + s * KSTR + h];
            sm[OFF_RED + sg * 64 + h] = a2;
        }
        __syncthreads();                               // B3
        if (tid < Hh) {
            float v = 0.f;
            #pragma unroll
            for (int sg = 0; sg < 6; sg++) v += sm[OFF_RED + sg * 64 + tid];
            out[(size_t)bw * Hh + tid] = v * inv;
        }
        // no 4th barrier: next-w writes (Ksm STS) only race with WS reads,
        // which completed at B3; e/wmax/wsum writes of w+1 are past B1(w+1).
    }
}

extern "C" void kernel_launch(void* const* d_in, const int* in_sizes, int n_in,
                              void* d_out, int out_size) {
    const float* query          = (const float*)d_in[0];
    const float* key            = (const float*)d_in[1];
    const float* W1             = (const float*)d_in[2];
    const float* b1             = (const float*)d_in[3];
    const float* prelu_a        = (const float*)d_in[4];
    const float* W2             = (const float*)d_in[5];
    const float* b2             = (const float*)d_in[6];
    const void*  mask           = (const void*)d_in[7];
    float* out = (float*)d_out;

    const int smem_bytes = SMEM_FLOATS * sizeof(float);   // ~69.0 KB
    cudaFuncSetAttribute(twb_all,
                         cudaFuncAttributeMaxDynamicSharedMemorySize, smem_bytes);
    twb_all<<<512, NT, smem_bytes>>>(query, key, W1, b1, prelu_a, W2, b2,
                                     mask, out);
}